// round 3
// baseline (speedup 1.0000x reference)
#include <cuda_runtime.h>
#include <cstdint>

// Problem constants (GAE_90589450207433)
#define N_NODES 100000
#define N_EDGES 3200000
#define IN_CH   256
#define HID     256
#define OUTC    128

// ---------------- device scratch (no allocs allowed) ----------------
__device__ int   g_deg[N_NODES];             // degree incl. self loop
__device__ int   g_row_ptr[N_NODES + 1];     // CSR row pointers (edges only)
__device__ int   g_cursor[N_NODES];          // scatter cursors
__device__ float g_dinv[N_NODES];            // deg^-1/2
__device__ int   g_csr_src[N_EDGES];         // CSR column (src) indices
__device__ __align__(16) float g_hp1[(size_t)N_NODES * HID];   // dinv * (x @ W1)
__device__ __align__(16) float g_h2 [(size_t)N_NODES * HID];   // relu(layer1 out)
__device__ __align__(16) float g_hp2[(size_t)N_NODES * OUTC];  // dinv * (h2 @ W2)

// ---------------- degree / norm ----------------
__global__ void init_deg_kernel() {
    int i = blockIdx.x * blockDim.x + threadIdx.x;
    if (i < N_NODES) g_deg[i] = 1;  // self loop
}

// edge_index is int32 on the wire (JAX x64 disabled downcasts int64 -> int32).
__global__ void count_deg_kernel(const int* __restrict__ edge_index) {
    int e = blockIdx.x * blockDim.x + threadIdx.x;
    if (e < N_EDGES) {
        int d = edge_index[N_EDGES + e];  // dst row
        if (d >= 0 && d < N_NODES) atomicAdd(&g_deg[d], 1);
    }
}

__global__ void dinv_kernel() {
    int i = blockIdx.x * blockDim.x + threadIdx.x;
    if (i < N_NODES) g_dinv[i] = rsqrtf((float)g_deg[i]);
}

// Single-block exclusive scan of (deg-1) -> row_ptr, cursor
__global__ void scan_kernel() {
    __shared__ int sums[1024];
    const int n = N_NODES;
    const int chunk = (n + 1023) / 1024;
    int tid = threadIdx.x;
    int start = tid * chunk;
    int end = start + chunk; if (end > n) end = n;
    if (start > n) start = n;

    int s = 0;
    for (int i = start; i < end; i++) s += g_deg[i] - 1;
    sums[tid] = s;
    __syncthreads();
    // inclusive Hillis-Steele scan
    for (int off = 1; off < 1024; off <<= 1) {
        int v = (tid >= off) ? sums[tid - off] : 0;
        __syncthreads();
        sums[tid] += v;
        __syncthreads();
    }
    int offset = (tid == 0) ? 0 : sums[tid - 1];
    for (int i = start; i < end; i++) {
        g_row_ptr[i] = offset;
        g_cursor[i]  = offset;
        offset += g_deg[i] - 1;
    }
    if (tid == 0) g_row_ptr[n] = sums[1023];
}

__global__ void build_csr_kernel(const int* __restrict__ edge_index) {
    int e = blockIdx.x * blockDim.x + threadIdx.x;
    if (e < N_EDGES) {
        int s = edge_index[e];
        int d = edge_index[N_EDGES + e];
        if (d >= 0 && d < N_NODES && s >= 0 && s < N_NODES) {
            int pos = atomicAdd(&g_cursor[d], 1);
            g_csr_src[pos] = s;
        }
    }
}

// ---------------- dense GEMM: C[row] = dinv[row] * (A @ B)[row] ----------------
// MODE 0: A = arg (x), C = g_hp1.   MODE 1: A = g_h2, C = g_hp2.
// BM=128, BN=64, BK=16, 256 threads, each thread 8x4 outputs
template <int MODE>
__global__ __launch_bounds__(256) void gemm_scale_kernel(
    const float* __restrict__ Aarg, const float* __restrict__ B,
    int M, int K, int N)
{
    const float* __restrict__ A = (MODE == 0) ? Aarg : g_h2;
    float* __restrict__ C = (MODE == 0) ? g_hp1 : g_hp2;

    const int BM = 128, BN = 64, BK = 16, TM = 8, TN = 4;
    __shared__ float As[BK][BM];
    __shared__ float Bs[BK][BN];

    int bm = blockIdx.x * BM;
    int bn = blockIdx.y * BN;
    int tid = threadIdx.x;
    int tx = tid & 15;   // 0..15
    int ty = tid >> 4;   // 0..15

    float acc[TM][TN];
#pragma unroll
    for (int i = 0; i < TM; i++)
#pragma unroll
        for (int j = 0; j < TN; j++) acc[i][j] = 0.f;

    int a_r = tid >> 2;          // 0..63
    int a_c = (tid & 3) * 4;     // 0,4,8,12
    int b_r = tid >> 4;          // 0..15
    int b_c = (tid & 15) * 4;    // 0..60

    for (int k0 = 0; k0 < K; k0 += BK) {
#pragma unroll
        for (int half = 0; half < 2; half++) {
            int row = bm + a_r + half * 64;
            float4 v = make_float4(0.f, 0.f, 0.f, 0.f);
            if (row < M) v = *(const float4*)&A[(size_t)row * K + k0 + a_c];
            As[a_c + 0][a_r + half * 64] = v.x;
            As[a_c + 1][a_r + half * 64] = v.y;
            As[a_c + 2][a_r + half * 64] = v.z;
            As[a_c + 3][a_r + half * 64] = v.w;
        }
        {
            float4 bv = *(const float4*)&B[(size_t)(k0 + b_r) * N + bn + b_c];
            *(float4*)&Bs[b_r][b_c] = bv;
        }
        __syncthreads();

#pragma unroll
        for (int k = 0; k < BK; k++) {
            float4 a0 = *(const float4*)&As[k][ty * TM];
            float4 a1 = *(const float4*)&As[k][ty * TM + 4];
            float4 b0 = *(const float4*)&Bs[k][tx * TN];
            float ar[TM] = {a0.x, a0.y, a0.z, a0.w, a1.x, a1.y, a1.z, a1.w};
            float br[TN] = {b0.x, b0.y, b0.z, b0.w};
#pragma unroll
            for (int i = 0; i < TM; i++)
#pragma unroll
                for (int j = 0; j < TN; j++)
                    acc[i][j] = fmaf(ar[i], br[j], acc[i][j]);
        }
        __syncthreads();
    }

#pragma unroll
    for (int i = 0; i < TM; i++) {
        int row = bm + ty * TM + i;
        if (row < M) {
            float scale = g_dinv[row];
            float4 r = make_float4(acc[i][0] * scale, acc[i][1] * scale,
                                   acc[i][2] * scale, acc[i][3] * scale);
            *(float4*)&C[(size_t)row * N + bn + tx * TN] = r;
        }
    }
}

// ---------------- SpMM aggregation: one warp per dst row ----------------
// out[i] = act( dinv[i] * (sum_{src in N(i)} hp[src] + hp[i]) + bias )
// MODE 0: hp = g_hp1, out = g_h2 (relu).  MODE 1: hp = g_hp2, out = arg (no relu).
template <int NF4, bool RELU, int MODE>
__global__ __launch_bounds__(256) void spmm_kernel(
    const float* __restrict__ bias, float* __restrict__ outarg)
{
    const float* __restrict__ hp = (MODE == 0) ? g_hp1 : g_hp2;
    float* __restrict__ out = (MODE == 0) ? g_h2 : outarg;

    const int ncol = NF4 * 128;
    int warp = (blockIdx.x * blockDim.x + threadIdx.x) >> 5;
    int lane = threadIdx.x & 31;
    if (warp >= N_NODES) return;
    int i = warp;

    const float4* selfp = (const float4*)(hp + (size_t)i * ncol);
    float4 acc[NF4];
#pragma unroll
    for (int c = 0; c < NF4; c++) acc[c] = selfp[lane + 32 * c];  // self loop

    int e = g_row_ptr[i];
    int end = g_row_ptr[i + 1];

    // 2-wide unroll for MLP
    for (; e + 1 < end; e += 2) {
        int s0 = g_csr_src[e];
        int s1 = g_csr_src[e + 1];
        const float4* p0 = (const float4*)(hp + (size_t)s0 * ncol);
        const float4* p1 = (const float4*)(hp + (size_t)s1 * ncol);
        float4 v0[NF4], v1[NF4];
#pragma unroll
        for (int c = 0; c < NF4; c++) v0[c] = p0[lane + 32 * c];
#pragma unroll
        for (int c = 0; c < NF4; c++) v1[c] = p1[lane + 32 * c];
#pragma unroll
        for (int c = 0; c < NF4; c++) {
            acc[c].x += v0[c].x + v1[c].x;
            acc[c].y += v0[c].y + v1[c].y;
            acc[c].z += v0[c].z + v1[c].z;
            acc[c].w += v0[c].w + v1[c].w;
        }
    }
    if (e < end) {
        int s0 = g_csr_src[e];
        const float4* p0 = (const float4*)(hp + (size_t)s0 * ncol);
#pragma unroll
        for (int c = 0; c < NF4; c++) {
            float4 v = p0[lane + 32 * c];
            acc[c].x += v.x; acc[c].y += v.y; acc[c].z += v.z; acc[c].w += v.w;
        }
    }

    float di = g_dinv[i];
    float4* op = (float4*)(out + (size_t)i * ncol);
#pragma unroll
    for (int c = 0; c < NF4; c++) {
        float4 bv = ((const float4*)bias)[lane + 32 * c];
        float4 r;
        r.x = fmaf(di, acc[c].x, bv.x);
        r.y = fmaf(di, acc[c].y, bv.y);
        r.z = fmaf(di, acc[c].z, bv.z);
        r.w = fmaf(di, acc[c].w, bv.w);
        if (RELU) {
            r.x = fmaxf(r.x, 0.f); r.y = fmaxf(r.y, 0.f);
            r.z = fmaxf(r.z, 0.f); r.w = fmaxf(r.w, 0.f);
        }
        op[lane + 32 * c] = r;
    }
}

// ---------------- launch ----------------
extern "C" void kernel_launch(void* const* d_in, const int* in_sizes, int n_in,
                              void* d_out, int out_size) {
    const float* x  = (const float*)d_in[0];
    const int*   ei = (const int*)d_in[1];      // int32 edge_index, [2, E]
    const float* W1 = (const float*)d_in[2];
    const float* b1 = (const float*)d_in[3];
    const float* W2 = (const float*)d_in[4];
    const float* b2 = (const float*)d_in[5];
    float* out = (float*)d_out;

    const int T = 256;
    int nb_nodes = (N_NODES + T - 1) / T;
    int nb_edges = (N_EDGES + T - 1) / T;

    // 1) GCN normalization + CSR build
    init_deg_kernel<<<nb_nodes, T>>>();
    count_deg_kernel<<<nb_edges, T>>>(ei);
    dinv_kernel<<<nb_nodes, T>>>();
    scan_kernel<<<1, 1024>>>();
    build_csr_kernel<<<nb_edges, T>>>(ei);

    // 2) Layer 1: hp1 = dinv * (x @ W1)
    {
        dim3 grid((N_NODES + 127) / 128, HID / 64);
        gemm_scale_kernel<0><<<grid, 256>>>(x, W1, N_NODES, IN_CH, HID);
    }
    // 3) Aggregate + bias + relu -> h2
    {
        int blocks = (N_NODES * 32 + T - 1) / T;
        spmm_kernel<2, true, 0><<<blocks, T>>>(b1, nullptr);
    }
    // 4) Layer 2: hp2 = dinv * (h2 @ W2)
    {
        dim3 grid((N_NODES + 127) / 128, OUTC / 64);
        gemm_scale_kernel<1><<<grid, 256>>>(nullptr, W2, N_NODES, HID, OUTC);
    }
    // 5) Aggregate + bias -> out
    {
        int blocks = (N_NODES * 32 + T - 1) / T;
        spmm_kernel<1, false, 1><<<blocks, T>>>(b2, out);
    }
}

// round 4
// speedup vs baseline: 1.1780x; 1.1780x over previous
#include <cuda_runtime.h>
#include <cstdint>

// Problem constants (GAE_90589450207433)
#define N_NODES 100000
#define N_EDGES 3200000
#define IN_CH   256
#define HID     256
#define OUTC    128

#define SCAN_T    256
#define SCAN_NB   ((N_NODES + SCAN_T - 1) / SCAN_T)   // 391 blocks

// ---------------- device scratch (no allocs allowed) ----------------
__device__ int   g_deg[N_NODES];             // degree incl. self loop
__device__ int   g_row_ptr[N_NODES + 1];     // CSR row pointers (edges only)
__device__ int   g_cursor[N_NODES];          // scatter cursors
__device__ float g_dinv[N_NODES];            // deg^-1/2
__device__ int   g_csr_src[N_EDGES];         // CSR column (src) indices
__device__ int   g_block_sums[SCAN_NB];      // per-block sums of (deg-1)
__device__ int   g_block_offs[SCAN_NB];      // exclusive-scanned block offsets
__device__ __align__(16) float g_hp1[(size_t)N_NODES * HID];   // dinv * (x @ W1)
__device__ __align__(16) float g_h2 [(size_t)N_NODES * HID];   // relu(layer1 out)
__device__ __align__(16) float g_hp2[(size_t)N_NODES * OUTC];  // dinv * (h2 @ W2)

// ---------------- degree / norm ----------------
__global__ void init_deg_kernel() {
    int i = blockIdx.x * blockDim.x + threadIdx.x;
    if (i < N_NODES) g_deg[i] = 1;  // self loop
}

// edge_index is int32 on the wire (JAX x64 disabled downcasts int64 -> int32).
__global__ void count_deg_kernel(const int* __restrict__ edge_index) {
    int e = blockIdx.x * blockDim.x + threadIdx.x;
    if (e < N_EDGES) {
        int d = edge_index[N_EDGES + e];  // dst row
        if (d >= 0 && d < N_NODES) atomicAdd(&g_deg[d], 1);
    }
}

__global__ void dinv_kernel() {
    int i = blockIdx.x * blockDim.x + threadIdx.x;
    if (i < N_NODES) g_dinv[i] = rsqrtf((float)g_deg[i]);
}

// ---------------- 3-phase multi-block exclusive scan of (deg-1) ----------------
// Phase 1: per-block sums
__global__ __launch_bounds__(SCAN_T) void scan_partial_kernel() {
    __shared__ int warp_sums[SCAN_T / 32];
    int i = blockIdx.x * SCAN_T + threadIdx.x;
    int v = (i < N_NODES) ? (g_deg[i] - 1) : 0;
    // warp reduce
    int s = v;
#pragma unroll
    for (int off = 16; off > 0; off >>= 1) s += __shfl_down_sync(0xffffffffu, s, off);
    int lane = threadIdx.x & 31;
    int wid  = threadIdx.x >> 5;
    if (lane == 0) warp_sums[wid] = s;
    __syncthreads();
    if (wid == 0) {
        int t = (lane < SCAN_T / 32) ? warp_sums[lane] : 0;
#pragma unroll
        for (int off = 16; off > 0; off >>= 1) t += __shfl_down_sync(0xffffffffu, t, off);
        if (lane == 0) g_block_sums[blockIdx.x] = t;
    }
}

// Phase 2: single block scans the block sums (SCAN_NB <= 1024)
__global__ __launch_bounds__(1024) void scan_blocksums_kernel() {
    __shared__ int sh[1024];
    int tid = threadIdx.x;
    int v = (tid < SCAN_NB) ? g_block_sums[tid] : 0;
    sh[tid] = v;
    __syncthreads();
    for (int off = 1; off < 1024; off <<= 1) {
        int t = (tid >= off) ? sh[tid - off] : 0;
        __syncthreads();
        sh[tid] += t;
        __syncthreads();
    }
    if (tid < SCAN_NB) g_block_offs[tid] = sh[tid] - v;  // exclusive
    if (tid == 0) g_row_ptr[N_NODES] = N_EDGES;          // total is known
}

// Phase 3: per-block exclusive scan + offset -> row_ptr, cursor
__global__ __launch_bounds__(SCAN_T) void scan_scatter_kernel() {
    __shared__ int warp_incl[SCAN_T / 32];
    int i = blockIdx.x * SCAN_T + threadIdx.x;
    int v = (i < N_NODES) ? (g_deg[i] - 1) : 0;
    int lane = threadIdx.x & 31;
    int wid  = threadIdx.x >> 5;
    // warp inclusive scan
    int incl = v;
#pragma unroll
    for (int off = 1; off < 32; off <<= 1) {
        int t = __shfl_up_sync(0xffffffffu, incl, off);
        if (lane >= off) incl += t;
    }
    if (lane == 31) warp_incl[wid] = incl;
    __syncthreads();
    if (wid == 0) {
        int t = (lane < SCAN_T / 32) ? warp_incl[lane] : 0;
#pragma unroll
        for (int off = 1; off < SCAN_T / 32; off <<= 1) {
            int u = __shfl_up_sync(0xffffffffu, t, off);
            if (lane >= off) t += u;
        }
        if (lane < SCAN_T / 32) warp_incl[lane] = t;
    }
    __syncthreads();
    int warp_off = (wid == 0) ? 0 : warp_incl[wid - 1];
    int excl = g_block_offs[blockIdx.x] + warp_off + (incl - v);
    if (i < N_NODES) {
        g_row_ptr[i] = excl;
        g_cursor[i]  = excl;
    }
}

__global__ void build_csr_kernel(const int* __restrict__ edge_index) {
    int e = blockIdx.x * blockDim.x + threadIdx.x;
    if (e < N_EDGES) {
        int s = edge_index[e];
        int d = edge_index[N_EDGES + e];
        if (d >= 0 && d < N_NODES && s >= 0 && s < N_NODES) {
            int pos = atomicAdd(&g_cursor[d], 1);
            g_csr_src[pos] = s;
        }
    }
}

// ---------------- dense GEMM: C[row] = dinv[row] * (A @ B)[row] ----------------
// MODE 0: A = arg (x), C = g_hp1.   MODE 1: A = g_h2, C = g_hp2.
// BM=128, BN=64, BK=16, 256 threads, each thread 8x4 outputs
template <int MODE>
__global__ __launch_bounds__(256) void gemm_scale_kernel(
    const float* __restrict__ Aarg, const float* __restrict__ B,
    int M, int K, int N)
{
    const float* __restrict__ A = (MODE == 0) ? Aarg : g_h2;
    float* __restrict__ C = (MODE == 0) ? g_hp1 : g_hp2;

    const int BM = 128, BN = 64, BK = 16, TM = 8, TN = 4;
    __shared__ float As[BK][BM];
    __shared__ float Bs[BK][BN];

    int bm = blockIdx.x * BM;
    int bn = blockIdx.y * BN;
    int tid = threadIdx.x;
    int tx = tid & 15;   // 0..15
    int ty = tid >> 4;   // 0..15

    float acc[TM][TN];
#pragma unroll
    for (int i = 0; i < TM; i++)
#pragma unroll
        for (int j = 0; j < TN; j++) acc[i][j] = 0.f;

    int a_r = tid >> 2;          // 0..63
    int a_c = (tid & 3) * 4;     // 0,4,8,12
    int b_r = tid >> 4;          // 0..15
    int b_c = (tid & 15) * 4;    // 0..60

    for (int k0 = 0; k0 < K; k0 += BK) {
#pragma unroll
        for (int half = 0; half < 2; half++) {
            int row = bm + a_r + half * 64;
            float4 v = make_float4(0.f, 0.f, 0.f, 0.f);
            if (row < M) v = *(const float4*)&A[(size_t)row * K + k0 + a_c];
            As[a_c + 0][a_r + half * 64] = v.x;
            As[a_c + 1][a_r + half * 64] = v.y;
            As[a_c + 2][a_r + half * 64] = v.z;
            As[a_c + 3][a_r + half * 64] = v.w;
        }
        {
            float4 bv = *(const float4*)&B[(size_t)(k0 + b_r) * N + bn + b_c];
            *(float4*)&Bs[b_r][b_c] = bv;
        }
        __syncthreads();

#pragma unroll
        for (int k = 0; k < BK; k++) {
            float4 a0 = *(const float4*)&As[k][ty * TM];
            float4 a1 = *(const float4*)&As[k][ty * TM + 4];
            float4 b0 = *(const float4*)&Bs[k][tx * TN];
            float ar[TM] = {a0.x, a0.y, a0.z, a0.w, a1.x, a1.y, a1.z, a1.w};
            float br[TN] = {b0.x, b0.y, b0.z, b0.w};
#pragma unroll
            for (int i = 0; i < TM; i++)
#pragma unroll
                for (int j = 0; j < TN; j++)
                    acc[i][j] = fmaf(ar[i], br[j], acc[i][j]);
        }
        __syncthreads();
    }

#pragma unroll
    for (int i = 0; i < TM; i++) {
        int row = bm + ty * TM + i;
        if (row < M) {
            float scale = g_dinv[row];
            float4 r = make_float4(acc[i][0] * scale, acc[i][1] * scale,
                                   acc[i][2] * scale, acc[i][3] * scale);
            *(float4*)&C[(size_t)row * N + bn + tx * TN] = r;
        }
    }
}

// ---------------- SpMM aggregation: one warp per dst row ----------------
// out[i] = act( dinv[i] * (sum_{src in N(i)} hp[src] + hp[i]) + bias )
// MODE 0: hp = g_hp1, out = g_h2 (relu).  MODE 1: hp = g_hp2, out = arg (no relu).
template <int NF4, bool RELU, int MODE>
__global__ __launch_bounds__(256) void spmm_kernel(
    const float* __restrict__ bias, float* __restrict__ outarg)
{
    const float* __restrict__ hp = (MODE == 0) ? g_hp1 : g_hp2;
    float* __restrict__ out = (MODE == 0) ? g_h2 : outarg;

    const int ncol = NF4 * 128;
    int warp = (blockIdx.x * blockDim.x + threadIdx.x) >> 5;
    int lane = threadIdx.x & 31;
    if (warp >= N_NODES) return;
    int i = warp;

    const float4* selfp = (const float4*)(hp + (size_t)i * ncol);
    float4 acc[NF4];
#pragma unroll
    for (int c = 0; c < NF4; c++) acc[c] = selfp[lane + 32 * c];  // self loop

    int e = g_row_ptr[i];
    int end = g_row_ptr[i + 1];

    // 4-wide unroll for MLP
    for (; e + 3 < end; e += 4) {
        int s0 = g_csr_src[e];
        int s1 = g_csr_src[e + 1];
        int s2 = g_csr_src[e + 2];
        int s3 = g_csr_src[e + 3];
        const float4* p0 = (const float4*)(hp + (size_t)s0 * ncol);
        const float4* p1 = (const float4*)(hp + (size_t)s1 * ncol);
        const float4* p2 = (const float4*)(hp + (size_t)s2 * ncol);
        const float4* p3 = (const float4*)(hp + (size_t)s3 * ncol);
        float4 v0[NF4], v1[NF4], v2[NF4], v3[NF4];
#pragma unroll
        for (int c = 0; c < NF4; c++) v0[c] = p0[lane + 32 * c];
#pragma unroll
        for (int c = 0; c < NF4; c++) v1[c] = p1[lane + 32 * c];
#pragma unroll
        for (int c = 0; c < NF4; c++) v2[c] = p2[lane + 32 * c];
#pragma unroll
        for (int c = 0; c < NF4; c++) v3[c] = p3[lane + 32 * c];
#pragma unroll
        for (int c = 0; c < NF4; c++) {
            acc[c].x += (v0[c].x + v1[c].x) + (v2[c].x + v3[c].x);
            acc[c].y += (v0[c].y + v1[c].y) + (v2[c].y + v3[c].y);
            acc[c].z += (v0[c].z + v1[c].z) + (v2[c].z + v3[c].z);
            acc[c].w += (v0[c].w + v1[c].w) + (v2[c].w + v3[c].w);
        }
    }
    for (; e < end; e++) {
        int s0 = g_csr_src[e];
        const float4* p0 = (const float4*)(hp + (size_t)s0 * ncol);
#pragma unroll
        for (int c = 0; c < NF4; c++) {
            float4 v = p0[lane + 32 * c];
            acc[c].x += v.x; acc[c].y += v.y; acc[c].z += v.z; acc[c].w += v.w;
        }
    }

    float di = g_dinv[i];
    float4* op = (float4*)(out + (size_t)i * ncol);
#pragma unroll
    for (int c = 0; c < NF4; c++) {
        float4 bv = ((const float4*)bias)[lane + 32 * c];
        float4 r;
        r.x = fmaf(di, acc[c].x, bv.x);
        r.y = fmaf(di, acc[c].y, bv.y);
        r.z = fmaf(di, acc[c].z, bv.z);
        r.w = fmaf(di, acc[c].w, bv.w);
        if (RELU) {
            r.x = fmaxf(r.x, 0.f); r.y = fmaxf(r.y, 0.f);
            r.z = fmaxf(r.z, 0.f); r.w = fmaxf(r.w, 0.f);
        }
        op[lane + 32 * c] = r;
    }
}

// ---------------- launch ----------------
extern "C" void kernel_launch(void* const* d_in, const int* in_sizes, int n_in,
                              void* d_out, int out_size) {
    const float* x  = (const float*)d_in[0];
    const int*   ei = (const int*)d_in[1];      // int32 edge_index, [2, E]
    const float* W1 = (const float*)d_in[2];
    const float* b1 = (const float*)d_in[3];
    const float* W2 = (const float*)d_in[4];
    const float* b2 = (const float*)d_in[5];
    float* out = (float*)d_out;

    const int T = 256;
    int nb_nodes = (N_NODES + T - 1) / T;
    int nb_edges = (N_EDGES + T - 1) / T;

    // 1) GCN normalization + CSR build
    init_deg_kernel<<<nb_nodes, T>>>();
    count_deg_kernel<<<nb_edges, T>>>(ei);
    dinv_kernel<<<nb_nodes, T>>>();
    scan_partial_kernel<<<SCAN_NB, SCAN_T>>>();
    scan_blocksums_kernel<<<1, 1024>>>();
    scan_scatter_kernel<<<SCAN_NB, SCAN_T>>>();
    build_csr_kernel<<<nb_edges, T>>>(ei);

    // 2) Layer 1: hp1 = dinv * (x @ W1)
    {
        dim3 grid((N_NODES + 127) / 128, HID / 64);
        gemm_scale_kernel<0><<<grid, 256>>>(x, W1, N_NODES, IN_CH, HID);
    }
    // 3) Aggregate + bias + relu -> h2
    {
        int blocks = (N_NODES * 32 + T - 1) / T;
        spmm_kernel<2, true, 0><<<blocks, T>>>(b1, nullptr);
    }
    // 4) Layer 2: hp2 = dinv * (h2 @ W2)
    {
        dim3 grid((N_NODES + 127) / 128, OUTC / 64);
        gemm_scale_kernel<1><<<grid, 256>>>(nullptr, W2, N_NODES, HID, OUTC);
    }
    // 5) Aggregate + bias -> out
    {
        int blocks = (N_NODES * 32 + T - 1) / T;
        spmm_kernel<1, false, 1><<<blocks, T>>>(b2, out);
    }
}

// round 5
// speedup vs baseline: 1.7476x; 1.4835x over previous
#include <cuda_runtime.h>
#include <cstdint>

// Problem constants (GAE_90589450207433)
#define N_NODES 100000
#define N_EDGES 3200000
#define IN_CH   256
#define HID     256
#define OUTC    128

#define SCAN_T    256
#define SCAN_NB   ((N_NODES + SCAN_T - 1) / SCAN_T)

// ---------------- device scratch (no allocs allowed) ----------------
__device__ int   g_deg[N_NODES];
__device__ int   g_row_ptr[N_NODES + 1];
__device__ int   g_cursor[N_NODES];
__device__ float g_dinv[N_NODES];
__device__ int   g_csr_src[N_EDGES];
__device__ int   g_block_sums[SCAN_NB];
__device__ int   g_block_offs[SCAN_NB];
__device__ __align__(16) float g_hp1[(size_t)N_NODES * HID];
__device__ __align__(16) float g_h2 [(size_t)N_NODES * HID];
__device__ __align__(16) float g_hp2[(size_t)N_NODES * OUTC];

// ---------------- degree / norm ----------------
__global__ void init_deg_kernel() {
    int i = blockIdx.x * blockDim.x + threadIdx.x;
    if (i < N_NODES) g_deg[i] = 1;
}

__global__ void count_deg_kernel(const int* __restrict__ edge_index) {
    int e = blockIdx.x * blockDim.x + threadIdx.x;
    if (e < N_EDGES) {
        int d = edge_index[N_EDGES + e];
        if (d >= 0 && d < N_NODES) atomicAdd(&g_deg[d], 1);
    }
}

__global__ void dinv_kernel() {
    int i = blockIdx.x * blockDim.x + threadIdx.x;
    if (i < N_NODES) g_dinv[i] = rsqrtf((float)g_deg[i]);
}

// ---------------- 3-phase multi-block exclusive scan of (deg-1) ----------------
__global__ __launch_bounds__(SCAN_T) void scan_partial_kernel() {
    __shared__ int warp_sums[SCAN_T / 32];
    int i = blockIdx.x * SCAN_T + threadIdx.x;
    int v = (i < N_NODES) ? (g_deg[i] - 1) : 0;
    int s = v;
#pragma unroll
    for (int off = 16; off > 0; off >>= 1) s += __shfl_down_sync(0xffffffffu, s, off);
    int lane = threadIdx.x & 31;
    int wid  = threadIdx.x >> 5;
    if (lane == 0) warp_sums[wid] = s;
    __syncthreads();
    if (wid == 0) {
        int t = (lane < SCAN_T / 32) ? warp_sums[lane] : 0;
#pragma unroll
        for (int off = 16; off > 0; off >>= 1) t += __shfl_down_sync(0xffffffffu, t, off);
        if (lane == 0) g_block_sums[blockIdx.x] = t;
    }
}

__global__ __launch_bounds__(1024) void scan_blocksums_kernel() {
    __shared__ int sh[1024];
    int tid = threadIdx.x;
    int v = (tid < SCAN_NB) ? g_block_sums[tid] : 0;
    sh[tid] = v;
    __syncthreads();
    for (int off = 1; off < 1024; off <<= 1) {
        int t = (tid >= off) ? sh[tid - off] : 0;
        __syncthreads();
        sh[tid] += t;
        __syncthreads();
    }
    if (tid < SCAN_NB) g_block_offs[tid] = sh[tid] - v;
    if (tid == 0) g_row_ptr[N_NODES] = N_EDGES;
}

__global__ __launch_bounds__(SCAN_T) void scan_scatter_kernel() {
    __shared__ int warp_incl[SCAN_T / 32];
    int i = blockIdx.x * SCAN_T + threadIdx.x;
    int v = (i < N_NODES) ? (g_deg[i] - 1) : 0;
    int lane = threadIdx.x & 31;
    int wid  = threadIdx.x >> 5;
    int incl = v;
#pragma unroll
    for (int off = 1; off < 32; off <<= 1) {
        int t = __shfl_up_sync(0xffffffffu, incl, off);
        if (lane >= off) incl += t;
    }
    if (lane == 31) warp_incl[wid] = incl;
    __syncthreads();
    if (wid == 0) {
        int t = (lane < SCAN_T / 32) ? warp_incl[lane] : 0;
#pragma unroll
        for (int off = 1; off < SCAN_T / 32; off <<= 1) {
            int u = __shfl_up_sync(0xffffffffu, t, off);
            if (lane >= off) t += u;
        }
        if (lane < SCAN_T / 32) warp_incl[lane] = t;
    }
    __syncthreads();
    int warp_off = (wid == 0) ? 0 : warp_incl[wid - 1];
    int excl = g_block_offs[blockIdx.x] + warp_off + (incl - v);
    if (i < N_NODES) {
        g_row_ptr[i] = excl;
        g_cursor[i]  = excl;
    }
}

__global__ void build_csr_kernel(const int* __restrict__ edge_index) {
    int e = blockIdx.x * blockDim.x + threadIdx.x;
    if (e < N_EDGES) {
        int s = edge_index[e];
        int d = edge_index[N_EDGES + e];
        if (d >= 0 && d < N_NODES && s >= 0 && s < N_NODES) {
            int pos = atomicAdd(&g_cursor[d], 1);
            g_csr_src[pos] = s;
        }
    }
}

// ---------------- TF32 tensor-core GEMM: C[row] = dinv[row] * (A @ B)[row] ----
__device__ __forceinline__ uint32_t f2tf32(float f) {
    uint32_t u;
    asm("cvt.rna.tf32.f32 %0, %1;" : "=r"(u) : "f"(f));
    return u;
}

__device__ __forceinline__ void mma_tf32(float* c, uint32_t a0, uint32_t a1,
                                         uint32_t a2, uint32_t a3,
                                         uint32_t b0, uint32_t b1) {
    asm volatile(
        "mma.sync.aligned.m16n8k8.row.col.f32.tf32.tf32.f32 "
        "{%0,%1,%2,%3}, {%4,%5,%6,%7}, {%8,%9}, {%0,%1,%2,%3};"
        : "+f"(c[0]), "+f"(c[1]), "+f"(c[2]), "+f"(c[3])
        : "r"(a0), "r"(a1), "r"(a2), "r"(a3), "r"(b0), "r"(b1));
}

// BM=128, BN=128, BK=32; 256 threads = 8 warps in 2(m) x 4(n); warp tile 64x32.
// MODE 0: A = arg (x), C = g_hp1.  MODE 1: A = g_h2, C = g_hp2.
#define APAD 4     // A smem stride = 36 floats (144B, 16B aligned)
#define BPAD 8     // B smem stride = 136 floats (544B, 16B aligned)
template <int MODE>
__global__ __launch_bounds__(256) void gemm_tf32_kernel(
    const float* __restrict__ Aarg, const float* __restrict__ B,
    int M, int K, int N)
{
    const float* __restrict__ A = (MODE == 0) ? Aarg : g_h2;
    float* __restrict__ C = (MODE == 0) ? g_hp1 : g_hp2;

    const int BM = 128, BN = 128, BK = 32;
    __shared__ uint32_t As[BM][BK + APAD];
    __shared__ uint32_t Bs[BK][BN + BPAD];

    int bm = blockIdx.x * BM;
    int bn = blockIdx.y * BN;
    int tid = threadIdx.x;
    int lane = tid & 31;
    int wid  = tid >> 5;
    int warp_m = wid & 1;    // 0..1 -> 64 rows each
    int warp_n = wid >> 1;   // 0..3 -> 32 cols each

    float acc[4][4][4];
#pragma unroll
    for (int mf = 0; mf < 4; mf++)
#pragma unroll
        for (int nf = 0; nf < 4; nf++)
#pragma unroll
            for (int c = 0; c < 4; c++) acc[mf][nf][c] = 0.f;

    int ar  = tid >> 3;          // 0..31
    int ac4 = (tid & 7) * 4;     // 0..28
    int br  = tid >> 5;          // 0..7
    int bc4 = (tid & 31) * 4;    // 0..124

    for (int k0 = 0; k0 < K; k0 += BK) {
        // Load A tile 128x32 (fp32 -> tf32 bits)
#pragma unroll
        for (int rr = 0; rr < 4; rr++) {
            int row = bm + ar + rr * 32;
            float4 v = make_float4(0.f, 0.f, 0.f, 0.f);
            if (row < M) v = *(const float4*)&A[(size_t)row * K + k0 + ac4];
            As[ar + rr * 32][ac4 + 0] = f2tf32(v.x);
            As[ar + rr * 32][ac4 + 1] = f2tf32(v.y);
            As[ar + rr * 32][ac4 + 2] = f2tf32(v.z);
            As[ar + rr * 32][ac4 + 3] = f2tf32(v.w);
        }
        // Load B tile 32x128
#pragma unroll
        for (int rr = 0; rr < 4; rr++) {
            float4 v = *(const float4*)&B[(size_t)(k0 + br + rr * 8) * N + bn + bc4];
            Bs[br + rr * 8][bc4 + 0] = f2tf32(v.x);
            Bs[br + rr * 8][bc4 + 1] = f2tf32(v.y);
            Bs[br + rr * 8][bc4 + 2] = f2tf32(v.z);
            Bs[br + rr * 8][bc4 + 3] = f2tf32(v.w);
        }
        __syncthreads();

#pragma unroll
        for (int kk = 0; kk < BK; kk += 8) {
            uint32_t bf[4][2];
#pragma unroll
            for (int nf = 0; nf < 4; nf++) {
                int col = warp_n * 32 + nf * 8 + (lane >> 2);
                bf[nf][0] = Bs[kk + (lane & 3)][col];
                bf[nf][1] = Bs[kk + (lane & 3) + 4][col];
            }
#pragma unroll
            for (int mf = 0; mf < 4; mf++) {
                int row = warp_m * 64 + mf * 16 + (lane >> 2);
                uint32_t a0 = As[row][kk + (lane & 3)];
                uint32_t a1 = As[row + 8][kk + (lane & 3)];
                uint32_t a2 = As[row][kk + (lane & 3) + 4];
                uint32_t a3 = As[row + 8][kk + (lane & 3) + 4];
#pragma unroll
                for (int nf = 0; nf < 4; nf++)
                    mma_tf32(acc[mf][nf], a0, a1, a2, a3, bf[nf][0], bf[nf][1]);
            }
        }
        __syncthreads();
    }

    // Epilogue: scale by dinv[row], store
#pragma unroll
    for (int mf = 0; mf < 4; mf++) {
        int r0 = bm + warp_m * 64 + mf * 16 + (lane >> 2);
        int r1 = r0 + 8;
        float d0 = (r0 < M) ? g_dinv[r0] : 0.f;
        float d1 = (r1 < M) ? g_dinv[r1] : 0.f;
#pragma unroll
        for (int nf = 0; nf < 4; nf++) {
            int cn = bn + warp_n * 32 + nf * 8 + (lane & 3) * 2;
            if (r0 < M) {
                float2 v = make_float2(acc[mf][nf][0] * d0, acc[mf][nf][1] * d0);
                *(float2*)&C[(size_t)r0 * N + cn] = v;
            }
            if (r1 < M) {
                float2 v = make_float2(acc[mf][nf][2] * d1, acc[mf][nf][3] * d1);
                *(float2*)&C[(size_t)r1 * N + cn] = v;
            }
        }
    }
}

// ---------------- SpMM aggregation: one warp per dst row ----------------
template <int NF4, bool RELU, int MODE>
__global__ __launch_bounds__(256) void spmm_kernel(
    const float* __restrict__ bias, float* __restrict__ outarg)
{
    const float* __restrict__ hp = (MODE == 0) ? g_hp1 : g_hp2;
    float* __restrict__ out = (MODE == 0) ? g_h2 : outarg;

    const int ncol = NF4 * 128;
    int warp = (blockIdx.x * blockDim.x + threadIdx.x) >> 5;
    int lane = threadIdx.x & 31;
    if (warp >= N_NODES) return;
    int i = warp;

    const float4* selfp = (const float4*)(hp + (size_t)i * ncol);
    float4 acc[NF4];
#pragma unroll
    for (int c = 0; c < NF4; c++) acc[c] = selfp[lane + 32 * c];

    int e = g_row_ptr[i];
    int end = g_row_ptr[i + 1];

    for (; e + 3 < end; e += 4) {
        int s0 = g_csr_src[e];
        int s1 = g_csr_src[e + 1];
        int s2 = g_csr_src[e + 2];
        int s3 = g_csr_src[e + 3];
        const float4* p0 = (const float4*)(hp + (size_t)s0 * ncol);
        const float4* p1 = (const float4*)(hp + (size_t)s1 * ncol);
        const float4* p2 = (const float4*)(hp + (size_t)s2 * ncol);
        const float4* p3 = (const float4*)(hp + (size_t)s3 * ncol);
        float4 v0[NF4], v1[NF4], v2[NF4], v3[NF4];
#pragma unroll
        for (int c = 0; c < NF4; c++) v0[c] = p0[lane + 32 * c];
#pragma unroll
        for (int c = 0; c < NF4; c++) v1[c] = p1[lane + 32 * c];
#pragma unroll
        for (int c = 0; c < NF4; c++) v2[c] = p2[lane + 32 * c];
#pragma unroll
        for (int c = 0; c < NF4; c++) v3[c] = p3[lane + 32 * c];
#pragma unroll
        for (int c = 0; c < NF4; c++) {
            acc[c].x += (v0[c].x + v1[c].x) + (v2[c].x + v3[c].x);
            acc[c].y += (v0[c].y + v1[c].y) + (v2[c].y + v3[c].y);
            acc[c].z += (v0[c].z + v1[c].z) + (v2[c].z + v3[c].z);
            acc[c].w += (v0[c].w + v1[c].w) + (v2[c].w + v3[c].w);
        }
    }
    for (; e < end; e++) {
        int s0 = g_csr_src[e];
        const float4* p0 = (const float4*)(hp + (size_t)s0 * ncol);
#pragma unroll
        for (int c = 0; c < NF4; c++) {
            float4 v = p0[lane + 32 * c];
            acc[c].x += v.x; acc[c].y += v.y; acc[c].z += v.z; acc[c].w += v.w;
        }
    }

    float di = g_dinv[i];
    float4* op = (float4*)(out + (size_t)i * ncol);
#pragma unroll
    for (int c = 0; c < NF4; c++) {
        float4 bv = ((const float4*)bias)[lane + 32 * c];
        float4 r;
        r.x = fmaf(di, acc[c].x, bv.x);
        r.y = fmaf(di, acc[c].y, bv.y);
        r.z = fmaf(di, acc[c].z, bv.z);
        r.w = fmaf(di, acc[c].w, bv.w);
        if (RELU) {
            r.x = fmaxf(r.x, 0.f); r.y = fmaxf(r.y, 0.f);
            r.z = fmaxf(r.z, 0.f); r.w = fmaxf(r.w, 0.f);
        }
        op[lane + 32 * c] = r;
    }
}

// ---------------- launch ----------------
extern "C" void kernel_launch(void* const* d_in, const int* in_sizes, int n_in,
                              void* d_out, int out_size) {
    const float* x  = (const float*)d_in[0];
    const int*   ei = (const int*)d_in[1];
    const float* W1 = (const float*)d_in[2];
    const float* b1 = (const float*)d_in[3];
    const float* W2 = (const float*)d_in[4];
    const float* b2 = (const float*)d_in[5];
    float* out = (float*)d_out;

    const int T = 256;
    int nb_nodes = (N_NODES + T - 1) / T;
    int nb_edges = (N_EDGES + T - 1) / T;

    // 1) GCN normalization + CSR build
    init_deg_kernel<<<nb_nodes, T>>>();
    count_deg_kernel<<<nb_edges, T>>>(ei);
    dinv_kernel<<<nb_nodes, T>>>();
    scan_partial_kernel<<<SCAN_NB, SCAN_T>>>();
    scan_blocksums_kernel<<<1, 1024>>>();
    scan_scatter_kernel<<<SCAN_NB, SCAN_T>>>();
    build_csr_kernel<<<nb_edges, T>>>(ei);

    // 2) Layer 1: hp1 = dinv * (x @ W1)  [tf32 tensor core]
    {
        dim3 grid((N_NODES + 127) / 128, HID / 128);
        gemm_tf32_kernel<0><<<grid, 256>>>(x, W1, N_NODES, IN_CH, HID);
    }
    // 3) Aggregate + bias + relu -> h2
    {
        int blocks = (N_NODES * 32 + T - 1) / T;
        spmm_kernel<2, true, 0><<<blocks, T>>>(b1, nullptr);
    }
    // 4) Layer 2: hp2 = dinv * (h2 @ W2)  [tf32 tensor core]
    {
        dim3 grid((N_NODES + 127) / 128, OUTC / 128);
        gemm_tf32_kernel<1><<<grid, 256>>>(nullptr, W2, N_NODES, HID, OUTC);
    }
    // 5) Aggregate + bias -> out
    {
        int blocks = (N_NODES * 32 + T - 1) / T;
        spmm_kernel<1, false, 1><<<blocks, T>>>(b2, out);
    }
}

// round 6
// speedup vs baseline: 2.3083x; 1.3208x over previous
#include <cuda_runtime.h>
#include <cuda_fp16.h>
#include <cstdint>

// Problem constants (GAE_90589450207433)
#define N_NODES 100000
#define N_EDGES 3200000
#define IN_CH   256
#define HID     256
#define OUTC    128

#define SCAN_T    256
#define SCAN_NB   ((N_NODES + SCAN_T - 1) / SCAN_T)

// ---------------- device scratch (no allocs allowed) ----------------
__device__ int   g_deg[N_NODES];
__device__ int   g_row_ptr[N_NODES + 1];
__device__ int   g_cursor[N_NODES];
__device__ float g_dinv[N_NODES];
__device__ int   g_csr_src[N_EDGES];
__device__ int   g_block_sums[SCAN_NB];
__device__ int   g_block_offs[SCAN_NB];
__device__ __align__(16) __half g_hp1h[(size_t)N_NODES * HID];   // fp16 gather table, layer 1
__device__ __align__(16) __half g_hp2h[(size_t)N_NODES * OUTC];  // fp16 gather table, layer 2
__device__ __align__(16) float  g_h2 [(size_t)N_NODES * HID];    // relu(layer1 out), fp32

// ---------------- degree / norm ----------------
__global__ void init_deg_kernel() {
    int i = blockIdx.x * blockDim.x + threadIdx.x;
    if (i < N_NODES) g_deg[i] = 1;
}

__global__ void count_deg_kernel(const int* __restrict__ edge_index) {
    int e = blockIdx.x * blockDim.x + threadIdx.x;
    if (e < N_EDGES) {
        int d = edge_index[N_EDGES + e];
        if (d >= 0 && d < N_NODES) atomicAdd(&g_deg[d], 1);
    }
}

__global__ void dinv_kernel() {
    int i = blockIdx.x * blockDim.x + threadIdx.x;
    if (i < N_NODES) g_dinv[i] = rsqrtf((float)g_deg[i]);
}

// ---------------- 3-phase multi-block exclusive scan of (deg-1) ----------------
__global__ __launch_bounds__(SCAN_T) void scan_partial_kernel() {
    __shared__ int warp_sums[SCAN_T / 32];
    int i = blockIdx.x * SCAN_T + threadIdx.x;
    int v = (i < N_NODES) ? (g_deg[i] - 1) : 0;
    int s = v;
#pragma unroll
    for (int off = 16; off > 0; off >>= 1) s += __shfl_down_sync(0xffffffffu, s, off);
    int lane = threadIdx.x & 31;
    int wid  = threadIdx.x >> 5;
    if (lane == 0) warp_sums[wid] = s;
    __syncthreads();
    if (wid == 0) {
        int t = (lane < SCAN_T / 32) ? warp_sums[lane] : 0;
#pragma unroll
        for (int off = 16; off > 0; off >>= 1) t += __shfl_down_sync(0xffffffffu, t, off);
        if (lane == 0) g_block_sums[blockIdx.x] = t;
    }
}

__global__ __launch_bounds__(1024) void scan_blocksums_kernel() {
    __shared__ int sh[1024];
    int tid = threadIdx.x;
    int v = (tid < SCAN_NB) ? g_block_sums[tid] : 0;
    sh[tid] = v;
    __syncthreads();
    for (int off = 1; off < 1024; off <<= 1) {
        int t = (tid >= off) ? sh[tid - off] : 0;
        __syncthreads();
        sh[tid] += t;
        __syncthreads();
    }
    if (tid < SCAN_NB) g_block_offs[tid] = sh[tid] - v;
    if (tid == 0) g_row_ptr[N_NODES] = N_EDGES;
}

__global__ __launch_bounds__(SCAN_T) void scan_scatter_kernel() {
    __shared__ int warp_incl[SCAN_T / 32];
    int i = blockIdx.x * SCAN_T + threadIdx.x;
    int v = (i < N_NODES) ? (g_deg[i] - 1) : 0;
    int lane = threadIdx.x & 31;
    int wid  = threadIdx.x >> 5;
    int incl = v;
#pragma unroll
    for (int off = 1; off < 32; off <<= 1) {
        int t = __shfl_up_sync(0xffffffffu, incl, off);
        if (lane >= off) incl += t;
    }
    if (lane == 31) warp_incl[wid] = incl;
    __syncthreads();
    if (wid == 0) {
        int t = (lane < SCAN_T / 32) ? warp_incl[lane] : 0;
#pragma unroll
        for (int off = 1; off < SCAN_T / 32; off <<= 1) {
            int u = __shfl_up_sync(0xffffffffu, t, off);
            if (lane >= off) t += u;
        }
        if (lane < SCAN_T / 32) warp_incl[lane] = t;
    }
    __syncthreads();
    int warp_off = (wid == 0) ? 0 : warp_incl[wid - 1];
    int excl = g_block_offs[blockIdx.x] + warp_off + (incl - v);
    if (i < N_NODES) {
        g_row_ptr[i] = excl;
        g_cursor[i]  = excl;
    }
}

__global__ void build_csr_kernel(const int* __restrict__ edge_index) {
    int e = blockIdx.x * blockDim.x + threadIdx.x;
    if (e < N_EDGES) {
        int s = edge_index[e];
        int d = edge_index[N_EDGES + e];
        if (d >= 0 && d < N_NODES && s >= 0 && s < N_NODES) {
            int pos = atomicAdd(&g_cursor[d], 1);
            g_csr_src[pos] = s;
        }
    }
}

// ---------------- TF32 tensor-core GEMM: Ch[row] = fp16(dinv[row] * (A@B)[row]) ----
__device__ __forceinline__ uint32_t f2tf32(float f) {
    uint32_t u;
    asm("cvt.rna.tf32.f32 %0, %1;" : "=r"(u) : "f"(f));
    return u;
}

__device__ __forceinline__ void mma_tf32(float* c, uint32_t a0, uint32_t a1,
                                         uint32_t a2, uint32_t a3,
                                         uint32_t b0, uint32_t b1) {
    asm volatile(
        "mma.sync.aligned.m16n8k8.row.col.f32.tf32.tf32.f32 "
        "{%0,%1,%2,%3}, {%4,%5,%6,%7}, {%8,%9}, {%0,%1,%2,%3};"
        : "+f"(c[0]), "+f"(c[1]), "+f"(c[2]), "+f"(c[3])
        : "r"(a0), "r"(a1), "r"(a2), "r"(a3), "r"(b0), "r"(b1));
}

// BM=128, BN=128, BK=32; 256 threads = 8 warps in 2(m) x 4(n); warp tile 64x32.
// MODE 0: A = arg (x), C = g_hp1h.  MODE 1: A = g_h2, C = g_hp2h.
#define APAD 4
#define BPAD 8
template <int MODE>
__global__ __launch_bounds__(256) void gemm_tf32_kernel(
    const float* __restrict__ Aarg, const float* __restrict__ B,
    int M, int K, int N)
{
    const float* __restrict__ A = (MODE == 0) ? Aarg : g_h2;
    __half* __restrict__ C = (MODE == 0) ? g_hp1h : g_hp2h;

    const int BM = 128, BN = 128, BK = 32;
    __shared__ uint32_t As[BM][BK + APAD];
    __shared__ uint32_t Bs[BK][BN + BPAD];

    int bm = blockIdx.x * BM;
    int bn = blockIdx.y * BN;
    int tid = threadIdx.x;
    int lane = tid & 31;
    int wid  = tid >> 5;
    int warp_m = wid & 1;
    int warp_n = wid >> 1;

    float acc[4][4][4];
#pragma unroll
    for (int mf = 0; mf < 4; mf++)
#pragma unroll
        for (int nf = 0; nf < 4; nf++)
#pragma unroll
            for (int c = 0; c < 4; c++) acc[mf][nf][c] = 0.f;

    int ar  = tid >> 3;
    int ac4 = (tid & 7) * 4;
    int br  = tid >> 5;
    int bc4 = (tid & 31) * 4;

    for (int k0 = 0; k0 < K; k0 += BK) {
#pragma unroll
        for (int rr = 0; rr < 4; rr++) {
            int row = bm + ar + rr * 32;
            float4 v = make_float4(0.f, 0.f, 0.f, 0.f);
            if (row < M) v = *(const float4*)&A[(size_t)row * K + k0 + ac4];
            As[ar + rr * 32][ac4 + 0] = f2tf32(v.x);
            As[ar + rr * 32][ac4 + 1] = f2tf32(v.y);
            As[ar + rr * 32][ac4 + 2] = f2tf32(v.z);
            As[ar + rr * 32][ac4 + 3] = f2tf32(v.w);
        }
#pragma unroll
        for (int rr = 0; rr < 4; rr++) {
            float4 v = *(const float4*)&B[(size_t)(k0 + br + rr * 8) * N + bn + bc4];
            Bs[br + rr * 8][bc4 + 0] = f2tf32(v.x);
            Bs[br + rr * 8][bc4 + 1] = f2tf32(v.y);
            Bs[br + rr * 8][bc4 + 2] = f2tf32(v.z);
            Bs[br + rr * 8][bc4 + 3] = f2tf32(v.w);
        }
        __syncthreads();

#pragma unroll
        for (int kk = 0; kk < BK; kk += 8) {
            uint32_t bf[4][2];
#pragma unroll
            for (int nf = 0; nf < 4; nf++) {
                int col = warp_n * 32 + nf * 8 + (lane >> 2);
                bf[nf][0] = Bs[kk + (lane & 3)][col];
                bf[nf][1] = Bs[kk + (lane & 3) + 4][col];
            }
#pragma unroll
            for (int mf = 0; mf < 4; mf++) {
                int row = warp_m * 64 + mf * 16 + (lane >> 2);
                uint32_t a0 = As[row][kk + (lane & 3)];
                uint32_t a1 = As[row + 8][kk + (lane & 3)];
                uint32_t a2 = As[row][kk + (lane & 3) + 4];
                uint32_t a3 = As[row + 8][kk + (lane & 3) + 4];
#pragma unroll
                for (int nf = 0; nf < 4; nf++)
                    mma_tf32(acc[mf][nf], a0, a1, a2, a3, bf[nf][0], bf[nf][1]);
            }
        }
        __syncthreads();
    }

    // Epilogue: scale by dinv[row], convert fp16, store half2
#pragma unroll
    for (int mf = 0; mf < 4; mf++) {
        int r0 = bm + warp_m * 64 + mf * 16 + (lane >> 2);
        int r1 = r0 + 8;
        float d0 = (r0 < M) ? g_dinv[r0] : 0.f;
        float d1 = (r1 < M) ? g_dinv[r1] : 0.f;
#pragma unroll
        for (int nf = 0; nf < 4; nf++) {
            int cn = bn + warp_n * 32 + nf * 8 + (lane & 3) * 2;
            if (r0 < M) {
                __half2 h = __floats2half2_rn(acc[mf][nf][0] * d0, acc[mf][nf][1] * d0);
                *(__half2*)&C[(size_t)r0 * N + cn] = h;
            }
            if (r1 < M) {
                __half2 h = __floats2half2_rn(acc[mf][nf][2] * d1, acc[mf][nf][3] * d1);
                *(__half2*)&C[(size_t)r1 * N + cn] = h;
            }
        }
    }
}

// ---------------- SpMM aggregation over fp16 tables: one warp per dst row ----
// out[i] = act( dinv[i] * (sum_{src in N(i)} hp[src] + hp[i]) + bias ), fp32 out
// NH = halves per lane (8 for 256 cols, 4 for 128 cols)
// MODE 0: hp = g_hp1h (256), out = g_h2, relu.  MODE 1: hp = g_hp2h (128), out = arg.
template <int NH, bool RELU, int MODE>
__global__ __launch_bounds__(256) void spmm_kernel(
    const float* __restrict__ bias, float* __restrict__ outarg)
{
    const __half* __restrict__ hp = (MODE == 0) ? g_hp1h : g_hp2h;
    float* __restrict__ out = (MODE == 0) ? g_h2 : outarg;

    const int ncol = NH * 32;
    int warp = (blockIdx.x * blockDim.x + threadIdx.x) >> 5;
    int lane = threadIdx.x & 31;
    if (warp >= N_NODES) return;
    int i = warp;

    float acc[NH];
    // self loop
    {
        const __half* p = hp + (size_t)i * ncol + lane * NH;
#pragma unroll
        for (int c = 0; c < NH; c += 2) {
            float2 v = __half22float2(*(const __half2*)&p[c]);
            acc[c] = v.x; acc[c + 1] = v.y;
        }
    }

    int e = g_row_ptr[i];
    int end = g_row_ptr[i + 1];

    for (; e + 3 < end; e += 4) {
        int s0 = g_csr_src[e];
        int s1 = g_csr_src[e + 1];
        int s2 = g_csr_src[e + 2];
        int s3 = g_csr_src[e + 3];
        const __half* p0 = hp + (size_t)s0 * ncol + lane * NH;
        const __half* p1 = hp + (size_t)s1 * ncol + lane * NH;
        const __half* p2 = hp + (size_t)s2 * ncol + lane * NH;
        const __half* p3 = hp + (size_t)s3 * ncol + lane * NH;
        __half2 v0[NH / 2], v1[NH / 2], v2[NH / 2], v3[NH / 2];
#pragma unroll
        for (int c = 0; c < NH / 2; c++) v0[c] = ((const __half2*)p0)[c];
#pragma unroll
        for (int c = 0; c < NH / 2; c++) v1[c] = ((const __half2*)p1)[c];
#pragma unroll
        for (int c = 0; c < NH / 2; c++) v2[c] = ((const __half2*)p2)[c];
#pragma unroll
        for (int c = 0; c < NH / 2; c++) v3[c] = ((const __half2*)p3)[c];
#pragma unroll
        for (int c = 0; c < NH / 2; c++) {
            float2 f0 = __half22float2(v0[c]);
            float2 f1 = __half22float2(v1[c]);
            float2 f2 = __half22float2(v2[c]);
            float2 f3 = __half22float2(v3[c]);
            acc[2 * c]     += (f0.x + f1.x) + (f2.x + f3.x);
            acc[2 * c + 1] += (f0.y + f1.y) + (f2.y + f3.y);
        }
    }
    for (; e < end; e++) {
        int s0 = g_csr_src[e];
        const __half* p0 = hp + (size_t)s0 * ncol + lane * NH;
#pragma unroll
        for (int c = 0; c < NH / 2; c++) {
            float2 f = __half22float2(((const __half2*)p0)[c]);
            acc[2 * c] += f.x; acc[2 * c + 1] += f.y;
        }
    }

    float di = g_dinv[i];
    float* op = out + (size_t)i * ncol + lane * NH;
    const float* bp = bias + lane * NH;
#pragma unroll
    for (int c = 0; c < NH; c += 4) {
        float4 bv = *(const float4*)&bp[c];
        float4 r;
        r.x = fmaf(di, acc[c + 0], bv.x);
        r.y = fmaf(di, acc[c + 1], bv.y);
        r.z = fmaf(di, acc[c + 2], bv.z);
        r.w = fmaf(di, acc[c + 3], bv.w);
        if (RELU) {
            r.x = fmaxf(r.x, 0.f); r.y = fmaxf(r.y, 0.f);
            r.z = fmaxf(r.z, 0.f); r.w = fmaxf(r.w, 0.f);
        }
        *(float4*)&op[c] = r;
    }
}

// ---------------- launch ----------------
extern "C" void kernel_launch(void* const* d_in, const int* in_sizes, int n_in,
                              void* d_out, int out_size) {
    const float* x  = (const float*)d_in[0];
    const int*   ei = (const int*)d_in[1];
    const float* W1 = (const float*)d_in[2];
    const float* b1 = (const float*)d_in[3];
    const float* W2 = (const float*)d_in[4];
    const float* b2 = (const float*)d_in[5];
    float* out = (float*)d_out;

    const int T = 256;
    int nb_nodes = (N_NODES + T - 1) / T;
    int nb_edges = (N_EDGES + T - 1) / T;

    // 1) GCN normalization + CSR build
    init_deg_kernel<<<nb_nodes, T>>>();
    count_deg_kernel<<<nb_edges, T>>>(ei);
    dinv_kernel<<<nb_nodes, T>>>();
    scan_partial_kernel<<<SCAN_NB, SCAN_T>>>();
    scan_blocksums_kernel<<<1, 1024>>>();
    scan_scatter_kernel<<<SCAN_NB, SCAN_T>>>();
    build_csr_kernel<<<nb_edges, T>>>(ei);

    // 2) Layer 1: hp1h = fp16(dinv * (x @ W1))  [tf32 tensor core]
    {
        dim3 grid((N_NODES + 127) / 128, HID / 128);
        gemm_tf32_kernel<0><<<grid, 256>>>(x, W1, N_NODES, IN_CH, HID);
    }
    // 3) Aggregate + bias + relu -> h2 (fp32)
    {
        int blocks = (N_NODES * 32 + T - 1) / T;
        spmm_kernel<8, true, 0><<<blocks, T>>>(b1, nullptr);
    }
    // 4) Layer 2: hp2h = fp16(dinv * (h2 @ W2))  [tf32 tensor core]
    {
        dim3 grid((N_NODES + 127) / 128, OUTC / 128);
        gemm_tf32_kernel<1><<<grid, 256>>>(nullptr, W2, N_NODES, HID, OUTC);
    }
    // 5) Aggregate + bias -> out (fp32)
    {
        int blocks = (N_NODES * 32 + T - 1) / T;
        spmm_kernel<4, false, 1><<<blocks, T>>>(b2, out);
    }
}

// round 7
// speedup vs baseline: 2.5870x; 1.1208x over previous
#include <cuda_runtime.h>
#include <cuda_fp16.h>
#include <cstdint>

// Problem constants (GAE_90589450207433)
#define N_NODES 100000
#define N_EDGES 3200000
#define IN_CH   256
#define HID     256
#define OUTC    128

#define SCAN_T    256
#define SCAN_NB   ((N_NODES + SCAN_T - 1) / SCAN_T)

// ---------------- device scratch (no allocs allowed) ----------------
__device__ int   g_deg[N_NODES];
__device__ int   g_row_ptr[N_NODES + 1];
__device__ int   g_cursor[N_NODES];
__device__ float g_dinv[N_NODES];
__device__ int   g_csr_src[N_EDGES];
__device__ int   g_block_sums[SCAN_NB];
__device__ int   g_block_offs[SCAN_NB];
__device__ __align__(16) __half g_hp1h[(size_t)N_NODES * HID];   // fp16 gather table, layer 1
__device__ __align__(16) __half g_hp2h[(size_t)N_NODES * OUTC];  // fp16 gather table, layer 2
__device__ __align__(16) __half g_h2h[(size_t)N_NODES * HID];    // relu(layer1 out), fp16

// ---------------- degree / norm ----------------
__global__ void init_deg_kernel() {
    int i = blockIdx.x * blockDim.x + threadIdx.x;
    if (i < N_NODES) g_deg[i] = 1;
}

__global__ void count_deg_kernel(const int* __restrict__ edge_index) {
    int e = blockIdx.x * blockDim.x + threadIdx.x;
    if (e < N_EDGES) {
        int d = edge_index[N_EDGES + e];
        if (d >= 0 && d < N_NODES) atomicAdd(&g_deg[d], 1);
    }
}

__global__ void dinv_kernel() {
    int i = blockIdx.x * blockDim.x + threadIdx.x;
    if (i < N_NODES) g_dinv[i] = rsqrtf((float)g_deg[i]);
}

// ---------------- 3-phase multi-block exclusive scan of (deg-1) ----------------
__global__ __launch_bounds__(SCAN_T) void scan_partial_kernel() {
    __shared__ int warp_sums[SCAN_T / 32];
    int i = blockIdx.x * SCAN_T + threadIdx.x;
    int v = (i < N_NODES) ? (g_deg[i] - 1) : 0;
    int s = v;
#pragma unroll
    for (int off = 16; off > 0; off >>= 1) s += __shfl_down_sync(0xffffffffu, s, off);
    int lane = threadIdx.x & 31;
    int wid  = threadIdx.x >> 5;
    if (lane == 0) warp_sums[wid] = s;
    __syncthreads();
    if (wid == 0) {
        int t = (lane < SCAN_T / 32) ? warp_sums[lane] : 0;
#pragma unroll
        for (int off = 16; off > 0; off >>= 1) t += __shfl_down_sync(0xffffffffu, t, off);
        if (lane == 0) g_block_sums[blockIdx.x] = t;
    }
}

__global__ __launch_bounds__(1024) void scan_blocksums_kernel() {
    __shared__ int sh[1024];
    int tid = threadIdx.x;
    int v = (tid < SCAN_NB) ? g_block_sums[tid] : 0;
    sh[tid] = v;
    __syncthreads();
    for (int off = 1; off < 1024; off <<= 1) {
        int t = (tid >= off) ? sh[tid - off] : 0;
        __syncthreads();
        sh[tid] += t;
        __syncthreads();
    }
    if (tid < SCAN_NB) g_block_offs[tid] = sh[tid] - v;
    if (tid == 0) g_row_ptr[N_NODES] = N_EDGES;
}

__global__ __launch_bounds__(SCAN_T) void scan_scatter_kernel() {
    __shared__ int warp_incl[SCAN_T / 32];
    int i = blockIdx.x * SCAN_T + threadIdx.x;
    int v = (i < N_NODES) ? (g_deg[i] - 1) : 0;
    int lane = threadIdx.x & 31;
    int wid  = threadIdx.x >> 5;
    int incl = v;
#pragma unroll
    for (int off = 1; off < 32; off <<= 1) {
        int t = __shfl_up_sync(0xffffffffu, incl, off);
        if (lane >= off) incl += t;
    }
    if (lane == 31) warp_incl[wid] = incl;
    __syncthreads();
    if (wid == 0) {
        int t = (lane < SCAN_T / 32) ? warp_incl[lane] : 0;
#pragma unroll
        for (int off = 1; off < SCAN_T / 32; off <<= 1) {
            int u = __shfl_up_sync(0xffffffffu, t, off);
            if (lane >= off) t += u;
        }
        if (lane < SCAN_T / 32) warp_incl[lane] = t;
    }
    __syncthreads();
    int warp_off = (wid == 0) ? 0 : warp_incl[wid - 1];
    int excl = g_block_offs[blockIdx.x] + warp_off + (incl - v);
    if (i < N_NODES) {
        g_row_ptr[i] = excl;
        g_cursor[i]  = excl;
    }
}

__global__ void build_csr_kernel(const int* __restrict__ edge_index) {
    int e = blockIdx.x * blockDim.x + threadIdx.x;
    if (e < N_EDGES) {
        int s = edge_index[e];
        int d = edge_index[N_EDGES + e];
        if (d >= 0 && d < N_NODES && s >= 0 && s < N_NODES) {
            int pos = atomicAdd(&g_cursor[d], 1);
            g_csr_src[pos] = s;
        }
    }
}

// ---------------- FP16 tensor-core GEMM: Ch[row] = fp16(dinv[row] * (A@B)[row]) ----
__device__ __forceinline__ void mma_f16(float* c, uint32_t a0, uint32_t a1,
                                        uint32_t a2, uint32_t a3,
                                        uint32_t b0, uint32_t b1) {
    asm volatile(
        "mma.sync.aligned.m16n8k16.row.col.f32.f16.f16.f32 "
        "{%0,%1,%2,%3}, {%4,%5,%6,%7}, {%8,%9}, {%0,%1,%2,%3};"
        : "+f"(c[0]), "+f"(c[1]), "+f"(c[2]), "+f"(c[3])
        : "r"(a0), "r"(a1), "r"(a2), "r"(a3), "r"(b0), "r"(b1));
}

// BM=128, BN=128, BK=32 (halves); 256 threads = 8 warps 2(m) x 4(n); warp tile 64x32.
// SMEM stores half2-packed u32.  A: [BM][BK/2 + APAD] (K-pairs along row).
// B: [BK/2][BN + BPAD], each u32 = half2(B[2k][n], B[2k+1][n])  (K-pairs packed).
// MODE 0: A = arg x (fp32->fp16), C = g_hp1h.  MODE 1: A = g_h2h (fp16), C = g_hp2h.
#define APAD 4     // A stride = 20 u32: rows land on disjoint bank quads
#define BPAD 8     // B stride = 136 u32: stride%32==8 -> 4 k-rows x 8 cols disjoint
template <int MODE>
__global__ __launch_bounds__(256) void gemm_f16_kernel(
    const float* __restrict__ Aarg, const float* __restrict__ B,
    int M, int K, int N)
{
    __half* __restrict__ C = (MODE == 0) ? g_hp1h : g_hp2h;

    const int BM = 128, BN = 128, BK = 32;   // BK in halves
    __shared__ uint32_t As[BM][BK / 2 + APAD];
    __shared__ uint32_t Bs[BK / 2][BN + BPAD];

    int bm = blockIdx.x * BM;
    int bn = blockIdx.y * BN;
    int tid = threadIdx.x;
    int lane = tid & 31;
    int wid  = tid >> 5;
    int warp_m = wid & 1;
    int warp_n = wid >> 1;

    float acc[4][4][4];
#pragma unroll
    for (int mf = 0; mf < 4; mf++)
#pragma unroll
        for (int nf = 0; nf < 4; nf++)
#pragma unroll
            for (int c = 0; c < 4; c++) acc[mf][nf][c] = 0.f;

    int ar  = tid >> 3;          // 0..31 (A row group)
    int ac4 = (tid & 7) * 4;     // fp32 col offset 0..28 (4 floats = 2 u32)
    int bk2 = tid >> 5;          // 0..7 (B k2-row, +8 for second)
    int bcg = (tid & 31) * 4;    // B col group (4 cols)

    for (int k0 = 0; k0 < K; k0 += BK) {
        // ---- load A tile: 128 rows x 32 halves ----
        if (MODE == 0) {
#pragma unroll
            for (int rr = 0; rr < 4; rr++) {
                int row = bm + ar + rr * 32;
                float4 v = make_float4(0.f, 0.f, 0.f, 0.f);
                if (row < M) v = *(const float4*)&Aarg[(size_t)row * K + k0 + ac4];
                __half2 h01 = __floats2half2_rn(v.x, v.y);
                __half2 h23 = __floats2half2_rn(v.z, v.w);
                As[ar + rr * 32][ac4 / 2]     = *(uint32_t*)&h01;
                As[ar + rr * 32][ac4 / 2 + 1] = *(uint32_t*)&h23;
            }
        } else {
            // fp16 source: row has 16 u32; each thread copies 2 u32 x 4 rows
#pragma unroll
            for (int rr = 0; rr < 4; rr++) {
                int row = bm + ar + rr * 32;
                uint2 v = make_uint2(0u, 0u);
                if (row < M) v = *(const uint2*)&g_h2h[(size_t)row * K + k0 + ac4];
                As[ar + rr * 32][ac4 / 2]     = v.x;
                As[ar + rr * 32][ac4 / 2 + 1] = v.y;
            }
        }
        // ---- load B tile: 32 k-rows x 128 cols, pack half2 along K ----
#pragma unroll
        for (int half = 0; half < 2; half++) {
            int k2 = bk2 + half * 8;                 // 0..15
            int gk = k0 + 2 * k2;
            float4 r0 = *(const float4*)&B[(size_t)gk * N + bn + bcg];
            float4 r1 = *(const float4*)&B[(size_t)(gk + 1) * N + bn + bcg];
            __half2 p0 = __floats2half2_rn(r0.x, r1.x);
            __half2 p1 = __floats2half2_rn(r0.y, r1.y);
            __half2 p2 = __floats2half2_rn(r0.z, r1.z);
            __half2 p3 = __floats2half2_rn(r0.w, r1.w);
            Bs[k2][bcg + 0] = *(uint32_t*)&p0;
            Bs[k2][bcg + 1] = *(uint32_t*)&p1;
            Bs[k2][bcg + 2] = *(uint32_t*)&p2;
            Bs[k2][bcg + 3] = *(uint32_t*)&p3;
        }
        __syncthreads();

#pragma unroll
        for (int kk = 0; kk < 2; kk++) {             // two k16 steps per BK=32
            uint32_t bf[4][2];
#pragma unroll
            for (int nf = 0; nf < 4; nf++) {
                int col = warp_n * 32 + nf * 8 + (lane >> 2);
                bf[nf][0] = Bs[kk * 8 + (lane & 3)][col];
                bf[nf][1] = Bs[kk * 8 + 4 + (lane & 3)][col];
            }
#pragma unroll
            for (int mf = 0; mf < 4; mf++) {
                int row = warp_m * 64 + mf * 16 + (lane >> 2);
                uint32_t a0 = As[row][kk * 8 + (lane & 3)];
                uint32_t a1 = As[row + 8][kk * 8 + (lane & 3)];
                uint32_t a2 = As[row][kk * 8 + 4 + (lane & 3)];
                uint32_t a3 = As[row + 8][kk * 8 + 4 + (lane & 3)];
#pragma unroll
                for (int nf = 0; nf < 4; nf++)
                    mma_f16(acc[mf][nf], a0, a1, a2, a3, bf[nf][0], bf[nf][1]);
            }
        }
        __syncthreads();
    }

    // Epilogue: scale by dinv[row], convert fp16, store half2
#pragma unroll
    for (int mf = 0; mf < 4; mf++) {
        int r0 = bm + warp_m * 64 + mf * 16 + (lane >> 2);
        int r1 = r0 + 8;
        float d0 = (r0 < M) ? g_dinv[r0] : 0.f;
        float d1 = (r1 < M) ? g_dinv[r1] : 0.f;
#pragma unroll
        for (int nf = 0; nf < 4; nf++) {
            int cn = bn + warp_n * 32 + nf * 8 + (lane & 3) * 2;
            if (r0 < M) {
                __half2 h = __floats2half2_rn(acc[mf][nf][0] * d0, acc[mf][nf][1] * d0);
                *(__half2*)&C[(size_t)r0 * N + cn] = h;
            }
            if (r1 < M) {
                __half2 h = __floats2half2_rn(acc[mf][nf][2] * d1, acc[mf][nf][3] * d1);
                *(__half2*)&C[(size_t)r1 * N + cn] = h;
            }
        }
    }
}

// ---------------- SpMM aggregation over fp16 tables: one warp per dst row ----
// out[i] = act( dinv[i] * (sum_{src in N(i)} hp[src] + hp[i]) + bias )
// NH = halves per lane (8 for 256 cols, 4 for 128 cols)
// MODE 0: hp = g_hp1h (256), out = g_h2h (fp16), relu.
// MODE 1: hp = g_hp2h (128), out = arg (fp32).
template <int NH, bool RELU, int MODE>
__global__ __launch_bounds__(256) void spmm_kernel(
    const float* __restrict__ bias, float* __restrict__ outarg)
{
    const __half* __restrict__ hp = (MODE == 0) ? g_hp1h : g_hp2h;

    const int ncol = NH * 32;
    int warp = (blockIdx.x * blockDim.x + threadIdx.x) >> 5;
    int lane = threadIdx.x & 31;
    if (warp >= N_NODES) return;
    int i = warp;

    float acc[NH];
    {
        const __half* p = hp + (size_t)i * ncol + lane * NH;
#pragma unroll
        for (int c = 0; c < NH; c += 2) {
            float2 v = __half22float2(*(const __half2*)&p[c]);
            acc[c] = v.x; acc[c + 1] = v.y;
        }
    }

    int e = g_row_ptr[i];
    int end = g_row_ptr[i + 1];

    for (; e + 3 < end; e += 4) {
        int s0 = g_csr_src[e];
        int s1 = g_csr_src[e + 1];
        int s2 = g_csr_src[e + 2];
        int s3 = g_csr_src[e + 3];
        const __half* p0 = hp + (size_t)s0 * ncol + lane * NH;
        const __half* p1 = hp + (size_t)s1 * ncol + lane * NH;
        const __half* p2 = hp + (size_t)s2 * ncol + lane * NH;
        const __half* p3 = hp + (size_t)s3 * ncol + lane * NH;
        __half2 v0[NH / 2], v1[NH / 2], v2[NH / 2], v3[NH / 2];
#pragma unroll
        for (int c = 0; c < NH / 2; c++) v0[c] = ((const __half2*)p0)[c];
#pragma unroll
        for (int c = 0; c < NH / 2; c++) v1[c] = ((const __half2*)p1)[c];
#pragma unroll
        for (int c = 0; c < NH / 2; c++) v2[c] = ((const __half2*)p2)[c];
#pragma unroll
        for (int c = 0; c < NH / 2; c++) v3[c] = ((const __half2*)p3)[c];
#pragma unroll
        for (int c = 0; c < NH / 2; c++) {
            float2 f0 = __half22float2(v0[c]);
            float2 f1 = __half22float2(v1[c]);
            float2 f2 = __half22float2(v2[c]);
            float2 f3 = __half22float2(v3[c]);
            acc[2 * c]     += (f0.x + f1.x) + (f2.x + f3.x);
            acc[2 * c + 1] += (f0.y + f1.y) + (f2.y + f3.y);
        }
    }
    for (; e < end; e++) {
        int s0 = g_csr_src[e];
        const __half* p0 = hp + (size_t)s0 * ncol + lane * NH;
#pragma unroll
        for (int c = 0; c < NH / 2; c++) {
            float2 f = __half22float2(((const __half2*)p0)[c]);
            acc[2 * c] += f.x; acc[2 * c + 1] += f.y;
        }
    }

    float di = g_dinv[i];
    const float* bp = bias + lane * NH;
    float r[NH];
#pragma unroll
    for (int c = 0; c < NH; c += 4) {
        float4 bv = *(const float4*)&bp[c];
        r[c + 0] = fmaf(di, acc[c + 0], bv.x);
        r[c + 1] = fmaf(di, acc[c + 1], bv.y);
        r[c + 2] = fmaf(di, acc[c + 2], bv.z);
        r[c + 3] = fmaf(di, acc[c + 3], bv.w);
        if (RELU) {
            r[c + 0] = fmaxf(r[c + 0], 0.f); r[c + 1] = fmaxf(r[c + 1], 0.f);
            r[c + 2] = fmaxf(r[c + 2], 0.f); r[c + 3] = fmaxf(r[c + 3], 0.f);
        }
    }

    if (MODE == 0) {
        __half* op = g_h2h + (size_t)i * ncol + lane * NH;
#pragma unroll
        for (int c = 0; c < NH; c += 2) {
            __half2 h = __floats2half2_rn(r[c], r[c + 1]);
            *(__half2*)&op[c] = h;
        }
    } else {
        float* op = outarg + (size_t)i * ncol + lane * NH;
#pragma unroll
        for (int c = 0; c < NH; c += 4)
            *(float4*)&op[c] = make_float4(r[c], r[c + 1], r[c + 2], r[c + 3]);
    }
}

// ---------------- launch ----------------
extern "C" void kernel_launch(void* const* d_in, const int* in_sizes, int n_in,
                              void* d_out, int out_size) {
    const float* x  = (const float*)d_in[0];
    const int*   ei = (const int*)d_in[1];
    const float* W1 = (const float*)d_in[2];
    const float* b1 = (const float*)d_in[3];
    const float* W2 = (const float*)d_in[4];
    const float* b2 = (const float*)d_in[5];
    float* out = (float*)d_out;

    const int T = 256;
    int nb_nodes = (N_NODES + T - 1) / T;
    int nb_edges = (N_EDGES + T - 1) / T;

    // 1) GCN normalization + CSR build
    init_deg_kernel<<<nb_nodes, T>>>();
    count_deg_kernel<<<nb_edges, T>>>(ei);
    dinv_kernel<<<nb_nodes, T>>>();
    scan_partial_kernel<<<SCAN_NB, SCAN_T>>>();
    scan_blocksums_kernel<<<1, 1024>>>();
    scan_scatter_kernel<<<SCAN_NB, SCAN_T>>>();
    build_csr_kernel<<<nb_edges, T>>>(ei);

    // 2) Layer 1: hp1h = fp16(dinv * (x @ W1))  [fp16 tensor core]
    {
        dim3 grid((N_NODES + 127) / 128, HID / 128);
        gemm_f16_kernel<0><<<grid, 256>>>(x, W1, N_NODES, IN_CH, HID);
    }
    // 3) Aggregate + bias + relu -> h2h (fp16)
    {
        int blocks = (N_NODES * 32 + T - 1) / T;
        spmm_kernel<8, true, 0><<<blocks, T>>>(b1, nullptr);
    }
    // 4) Layer 2: hp2h = fp16(dinv * (h2h @ W2))  [fp16 tensor core]
    {
        dim3 grid((N_NODES + 127) / 128, OUTC / 128);
        gemm_f16_kernel<1><<<grid, 256>>>(nullptr, W2, N_NODES, HID, OUTC);
    }
    // 5) Aggregate + bias -> out (fp32)
    {
        int blocks = (N_NODES * 32 + T - 1) / T;
        spmm_kernel<4, false, 1><<<blocks, T>>>(b2, out);
    }
}

// round 8
// speedup vs baseline: 2.7013x; 1.0442x over previous
#include <cuda_runtime.h>
#include <cuda_fp16.h>
#include <cstdint>

// Problem constants (GAE_90589450207433)
#define N_NODES 100000
#define N_EDGES 3200000
#define IN_CH   256
#define HID     256
#define OUTC    128

#define SCAN_T    256
#define SCAN_NB   ((N_NODES + SCAN_T - 1) / SCAN_T)

// ---------------- device scratch (no allocs allowed) ----------------
__device__ int   g_deg[N_NODES];
__device__ int   g_row_ptr[N_NODES + 1];
__device__ int   g_cursor[N_NODES];
__device__ float g_dinv[N_NODES];
__device__ int   g_csr_src[N_EDGES];
__device__ int   g_block_sums[SCAN_NB];
__device__ int   g_block_offs[SCAN_NB];
__device__ __align__(16) __half g_hp1h[(size_t)N_NODES * HID];   // fp16 gather table, layer 1
__device__ __align__(16) __half g_hp2h[(size_t)N_NODES * OUTC];  // fp16 gather table, layer 2
__device__ __align__(16) __half g_h2h[(size_t)N_NODES * HID];    // relu(layer1 out), fp16

// ---------------- degree / norm ----------------
__global__ void init_deg_kernel() {
    int i = blockIdx.x * blockDim.x + threadIdx.x;
    if (i < N_NODES) g_deg[i] = 1;
}

// 2 edges per thread, int2 loads
__global__ void count_deg_kernel(const int* __restrict__ edge_index) {
    int t = blockIdx.x * blockDim.x + threadIdx.x;
    int e = t * 2;
    if (e + 1 < N_EDGES) {
        int2 d = *(const int2*)&edge_index[N_EDGES + e];
        if (d.x >= 0 && d.x < N_NODES) atomicAdd(&g_deg[d.x], 1);
        if (d.y >= 0 && d.y < N_NODES) atomicAdd(&g_deg[d.y], 1);
    } else if (e < N_EDGES) {
        int d = edge_index[N_EDGES + e];
        if (d >= 0 && d < N_NODES) atomicAdd(&g_deg[d], 1);
    }
}

__global__ void dinv_kernel() {
    int i = blockIdx.x * blockDim.x + threadIdx.x;
    if (i < N_NODES) g_dinv[i] = rsqrtf((float)g_deg[i]);
}

// ---------------- 3-phase multi-block exclusive scan of (deg-1) ----------------
__global__ __launch_bounds__(SCAN_T) void scan_partial_kernel() {
    __shared__ int warp_sums[SCAN_T / 32];
    int i = blockIdx.x * SCAN_T + threadIdx.x;
    int v = (i < N_NODES) ? (g_deg[i] - 1) : 0;
    int s = v;
#pragma unroll
    for (int off = 16; off > 0; off >>= 1) s += __shfl_down_sync(0xffffffffu, s, off);
    int lane = threadIdx.x & 31;
    int wid  = threadIdx.x >> 5;
    if (lane == 0) warp_sums[wid] = s;
    __syncthreads();
    if (wid == 0) {
        int t = (lane < SCAN_T / 32) ? warp_sums[lane] : 0;
#pragma unroll
        for (int off = 16; off > 0; off >>= 1) t += __shfl_down_sync(0xffffffffu, t, off);
        if (lane == 0) g_block_sums[blockIdx.x] = t;
    }
}

__global__ __launch_bounds__(1024) void scan_blocksums_kernel() {
    __shared__ int sh[1024];
    int tid = threadIdx.x;
    int v = (tid < SCAN_NB) ? g_block_sums[tid] : 0;
    sh[tid] = v;
    __syncthreads();
    for (int off = 1; off < 1024; off <<= 1) {
        int t = (tid >= off) ? sh[tid - off] : 0;
        __syncthreads();
        sh[tid] += t;
        __syncthreads();
    }
    if (tid < SCAN_NB) g_block_offs[tid] = sh[tid] - v;
    if (tid == 0) g_row_ptr[N_NODES] = N_EDGES;
}

__global__ __launch_bounds__(SCAN_T) void scan_scatter_kernel() {
    __shared__ int warp_incl[SCAN_T / 32];
    int i = blockIdx.x * SCAN_T + threadIdx.x;
    int v = (i < N_NODES) ? (g_deg[i] - 1) : 0;
    int lane = threadIdx.x & 31;
    int wid  = threadIdx.x >> 5;
    int incl = v;
#pragma unroll
    for (int off = 1; off < 32; off <<= 1) {
        int t = __shfl_up_sync(0xffffffffu, incl, off);
        if (lane >= off) incl += t;
    }
    if (lane == 31) warp_incl[wid] = incl;
    __syncthreads();
    if (wid == 0) {
        int t = (lane < SCAN_T / 32) ? warp_incl[lane] : 0;
#pragma unroll
        for (int off = 1; off < SCAN_T / 32; off <<= 1) {
            int u = __shfl_up_sync(0xffffffffu, t, off);
            if (lane >= off) t += u;
        }
        if (lane < SCAN_T / 32) warp_incl[lane] = t;
    }
    __syncthreads();
    int warp_off = (wid == 0) ? 0 : warp_incl[wid - 1];
    int excl = g_block_offs[blockIdx.x] + warp_off + (incl - v);
    if (i < N_NODES) {
        g_row_ptr[i] = excl;
        g_cursor[i]  = excl;
    }
}

// 2 edges per thread, int2 loads of both rows
__global__ void build_csr_kernel(const int* __restrict__ edge_index) {
    int t = blockIdx.x * blockDim.x + threadIdx.x;
    int e = t * 2;
    if (e + 1 < N_EDGES) {
        int2 s = *(const int2*)&edge_index[e];
        int2 d = *(const int2*)&edge_index[N_EDGES + e];
        if (d.x >= 0 && d.x < N_NODES && s.x >= 0 && s.x < N_NODES) {
            int pos = atomicAdd(&g_cursor[d.x], 1);
            g_csr_src[pos] = s.x;
        }
        if (d.y >= 0 && d.y < N_NODES && s.y >= 0 && s.y < N_NODES) {
            int pos = atomicAdd(&g_cursor[d.y], 1);
            g_csr_src[pos] = s.y;
        }
    } else if (e < N_EDGES) {
        int s = edge_index[e];
        int d = edge_index[N_EDGES + e];
        if (d >= 0 && d < N_NODES && s >= 0 && s < N_NODES) {
            int pos = atomicAdd(&g_cursor[d], 1);
            g_csr_src[pos] = s;
        }
    }
}

// ---------------- FP16 tensor-core GEMM: Ch[row] = fp16(dinv[row] * (A@B)[row]) ----
__device__ __forceinline__ void mma_f16(float* c, uint32_t a0, uint32_t a1,
                                        uint32_t a2, uint32_t a3,
                                        uint32_t b0, uint32_t b1) {
    asm volatile(
        "mma.sync.aligned.m16n8k16.row.col.f32.f16.f16.f32 "
        "{%0,%1,%2,%3}, {%4,%5,%6,%7}, {%8,%9}, {%0,%1,%2,%3};"
        : "+f"(c[0]), "+f"(c[1]), "+f"(c[2]), "+f"(c[3])
        : "r"(a0), "r"(a1), "r"(a2), "r"(a3), "r"(b0), "r"(b1));
}

#define APAD 4
#define BPAD 8
template <int MODE>
__global__ __launch_bounds__(256) void gemm_f16_kernel(
    const float* __restrict__ Aarg, const float* __restrict__ B,
    int M, int K, int N)
{
    __half* __restrict__ C = (MODE == 0) ? g_hp1h : g_hp2h;

    const int BM = 128, BN = 128, BK = 32;   // BK in halves
    __shared__ uint32_t As[BM][BK / 2 + APAD];
    __shared__ uint32_t Bs[BK / 2][BN + BPAD];

    int bm = blockIdx.x * BM;
    int bn = blockIdx.y * BN;
    int tid = threadIdx.x;
    int lane = tid & 31;
    int wid  = tid >> 5;
    int warp_m = wid & 1;
    int warp_n = wid >> 1;

    float acc[4][4][4];
#pragma unroll
    for (int mf = 0; mf < 4; mf++)
#pragma unroll
        for (int nf = 0; nf < 4; nf++)
#pragma unroll
            for (int c = 0; c < 4; c++) acc[mf][nf][c] = 0.f;

    int ar  = tid >> 3;
    int ac4 = (tid & 7) * 4;
    int bk2 = tid >> 5;
    int bcg = (tid & 31) * 4;

    for (int k0 = 0; k0 < K; k0 += BK) {
        if (MODE == 0) {
#pragma unroll
            for (int rr = 0; rr < 4; rr++) {
                int row = bm + ar + rr * 32;
                float4 v = make_float4(0.f, 0.f, 0.f, 0.f);
                if (row < M) v = *(const float4*)&Aarg[(size_t)row * K + k0 + ac4];
                __half2 h01 = __floats2half2_rn(v.x, v.y);
                __half2 h23 = __floats2half2_rn(v.z, v.w);
                As[ar + rr * 32][ac4 / 2]     = *(uint32_t*)&h01;
                As[ar + rr * 32][ac4 / 2 + 1] = *(uint32_t*)&h23;
            }
        } else {
#pragma unroll
            for (int rr = 0; rr < 4; rr++) {
                int row = bm + ar + rr * 32;
                uint2 v = make_uint2(0u, 0u);
                if (row < M) v = *(const uint2*)&g_h2h[(size_t)row * K + k0 + ac4];
                As[ar + rr * 32][ac4 / 2]     = v.x;
                As[ar + rr * 32][ac4 / 2 + 1] = v.y;
            }
        }
#pragma unroll
        for (int half = 0; half < 2; half++) {
            int k2 = bk2 + half * 8;
            int gk = k0 + 2 * k2;
            float4 r0 = *(const float4*)&B[(size_t)gk * N + bn + bcg];
            float4 r1 = *(const float4*)&B[(size_t)(gk + 1) * N + bn + bcg];
            __half2 p0 = __floats2half2_rn(r0.x, r1.x);
            __half2 p1 = __floats2half2_rn(r0.y, r1.y);
            __half2 p2 = __floats2half2_rn(r0.z, r1.z);
            __half2 p3 = __floats2half2_rn(r0.w, r1.w);
            Bs[k2][bcg + 0] = *(uint32_t*)&p0;
            Bs[k2][bcg + 1] = *(uint32_t*)&p1;
            Bs[k2][bcg + 2] = *(uint32_t*)&p2;
            Bs[k2][bcg + 3] = *(uint32_t*)&p3;
        }
        __syncthreads();

#pragma unroll
        for (int kk = 0; kk < 2; kk++) {
            uint32_t bf[4][2];
#pragma unroll
            for (int nf = 0; nf < 4; nf++) {
                int col = warp_n * 32 + nf * 8 + (lane >> 2);
                bf[nf][0] = Bs[kk * 8 + (lane & 3)][col];
                bf[nf][1] = Bs[kk * 8 + 4 + (lane & 3)][col];
            }
#pragma unroll
            for (int mf = 0; mf < 4; mf++) {
                int row = warp_m * 64 + mf * 16 + (lane >> 2);
                uint32_t a0 = As[row][kk * 8 + (lane & 3)];
                uint32_t a1 = As[row + 8][kk * 8 + (lane & 3)];
                uint32_t a2 = As[row][kk * 8 + 4 + (lane & 3)];
                uint32_t a3 = As[row + 8][kk * 8 + 4 + (lane & 3)];
#pragma unroll
                for (int nf = 0; nf < 4; nf++)
                    mma_f16(acc[mf][nf], a0, a1, a2, a3, bf[nf][0], bf[nf][1]);
            }
        }
        __syncthreads();
    }

#pragma unroll
    for (int mf = 0; mf < 4; mf++) {
        int r0 = bm + warp_m * 64 + mf * 16 + (lane >> 2);
        int r1 = r0 + 8;
        float d0 = (r0 < M) ? g_dinv[r0] : 0.f;
        float d1 = (r1 < M) ? g_dinv[r1] : 0.f;
#pragma unroll
        for (int nf = 0; nf < 4; nf++) {
            int cn = bn + warp_n * 32 + nf * 8 + (lane & 3) * 2;
            if (r0 < M) {
                __half2 h = __floats2half2_rn(acc[mf][nf][0] * d0, acc[mf][nf][1] * d0);
                *(__half2*)&C[(size_t)r0 * N + cn] = h;
            }
            if (r1 < M) {
                __half2 h = __floats2half2_rn(acc[mf][nf][2] * d1, acc[mf][nf][3] * d1);
                *(__half2*)&C[(size_t)r1 * N + cn] = h;
            }
        }
    }
}

// ---------------- SpMM aggregation over fp16 tables: one warp per dst row ----
// VEC: u32 words per lane (4 for 256 cols -> uint4, 2 for 128 cols -> uint2)
// MODE 0: hp = g_hp1h (256), out = g_h2h (fp16), relu.
// MODE 1: hp = g_hp2h (128), out = arg (fp32).
template <int VEC, bool RELU, int MODE>
__global__ __launch_bounds__(256) void spmm_kernel(
    const float* __restrict__ bias, float* __restrict__ outarg)
{
    const uint32_t* __restrict__ hp =
        (const uint32_t*)((MODE == 0) ? (const __half*)g_hp1h : (const __half*)g_hp2h);

    const int ncol32 = VEC * 32;    // u32 words per row
    int warp = (blockIdx.x * blockDim.x + threadIdx.x) >> 5;
    int lane = threadIdx.x & 31;
    if (warp >= N_NODES) return;
    int i = warp;

    float acc[VEC * 2];
    {
        uint32_t v[VEC];
        const uint32_t* p = hp + (size_t)i * ncol32 + lane * VEC;
        if (VEC == 4) { uint4 u = *(const uint4*)p; v[0]=u.x; v[1]=u.y; v[2]=u.z; v[3]=u.w; }
        else          { uint2 u = *(const uint2*)p; v[0]=u.x; v[1]=u.y; }
#pragma unroll
        for (int c = 0; c < VEC; c++) {
            float2 f = __half22float2(*(__half2*)&v[c]);
            acc[2*c] = f.x; acc[2*c+1] = f.y;
        }
    }

    int e = g_row_ptr[i];
    int end = g_row_ptr[i + 1];

    for (; e + 3 < end; e += 4) {
        int s0 = g_csr_src[e];
        int s1 = g_csr_src[e + 1];
        int s2 = g_csr_src[e + 2];
        int s3 = g_csr_src[e + 3];
        uint32_t v0[VEC], v1[VEC], v2[VEC], v3[VEC];
        const uint32_t* p0 = hp + (size_t)s0 * ncol32 + lane * VEC;
        const uint32_t* p1 = hp + (size_t)s1 * ncol32 + lane * VEC;
        const uint32_t* p2 = hp + (size_t)s2 * ncol32 + lane * VEC;
        const uint32_t* p3 = hp + (size_t)s3 * ncol32 + lane * VEC;
        if (VEC == 4) {
            uint4 a = *(const uint4*)p0; v0[0]=a.x; v0[1]=a.y; v0[2]=a.z; v0[3]=a.w;
            uint4 b = *(const uint4*)p1; v1[0]=b.x; v1[1]=b.y; v1[2]=b.z; v1[3]=b.w;
            uint4 c = *(const uint4*)p2; v2[0]=c.x; v2[1]=c.y; v2[2]=c.z; v2[3]=c.w;
            uint4 d = *(const uint4*)p3; v3[0]=d.x; v3[1]=d.y; v3[2]=d.z; v3[3]=d.w;
        } else {
            uint2 a = *(const uint2*)p0; v0[0]=a.x; v0[1]=a.y;
            uint2 b = *(const uint2*)p1; v1[0]=b.x; v1[1]=b.y;
            uint2 c = *(const uint2*)p2; v2[0]=c.x; v2[1]=c.y;
            uint2 d = *(const uint2*)p3; v3[0]=d.x; v3[1]=d.y;
        }
#pragma unroll
        for (int c = 0; c < VEC; c++) {
            float2 f0 = __half22float2(*(__half2*)&v0[c]);
            float2 f1 = __half22float2(*(__half2*)&v1[c]);
            float2 f2 = __half22float2(*(__half2*)&v2[c]);
            float2 f3 = __half22float2(*(__half2*)&v3[c]);
            acc[2*c]   += (f0.x + f1.x) + (f2.x + f3.x);
            acc[2*c+1] += (f0.y + f1.y) + (f2.y + f3.y);
        }
    }
    for (; e < end; e++) {
        int s0 = g_csr_src[e];
        uint32_t v[VEC];
        const uint32_t* p = hp + (size_t)s0 * ncol32 + lane * VEC;
        if (VEC == 4) { uint4 u = *(const uint4*)p; v[0]=u.x; v[1]=u.y; v[2]=u.z; v[3]=u.w; }
        else          { uint2 u = *(const uint2*)p; v[0]=u.x; v[1]=u.y; }
#pragma unroll
        for (int c = 0; c < VEC; c++) {
            float2 f = __half22float2(*(__half2*)&v[c]);
            acc[2*c] += f.x; acc[2*c+1] += f.y;
        }
    }

    float di = g_dinv[i];
    const float* bp = bias + lane * VEC * 2;
    float r[VEC * 2];
#pragma unroll
    for (int c = 0; c < VEC * 2; c += 4) {
        float4 bv = *(const float4*)&bp[c];
        r[c + 0] = fmaf(di, acc[c + 0], bv.x);
        r[c + 1] = fmaf(di, acc[c + 1], bv.y);
        r[c + 2] = fmaf(di, acc[c + 2], bv.z);
        r[c + 3] = fmaf(di, acc[c + 3], bv.w);
        if (RELU) {
            r[c + 0] = fmaxf(r[c + 0], 0.f); r[c + 1] = fmaxf(r[c + 1], 0.f);
            r[c + 2] = fmaxf(r[c + 2], 0.f); r[c + 3] = fmaxf(r[c + 3], 0.f);
        }
    }

    if (MODE == 0) {
        uint32_t* op = (uint32_t*)g_h2h + (size_t)i * ncol32 + lane * VEC;
        uint32_t w[VEC];
#pragma unroll
        for (int c = 0; c < VEC; c++) {
            __half2 h = __floats2half2_rn(r[2*c], r[2*c+1]);
            w[c] = *(uint32_t*)&h;
        }
        if (VEC == 4) *(uint4*)op = make_uint4(w[0], w[1], w[2], w[3]);
        else          *(uint2*)op = make_uint2(w[0], w[1]);
    } else {
        float* op = outarg + (size_t)i * ncol32 * 2 + lane * VEC * 2;
#pragma unroll
        for (int c = 0; c < VEC * 2; c += 4)
            *(float4*)&op[c] = make_float4(r[c], r[c+1], r[c+2], r[c+3]);
    }
}

// ---------------- launch ----------------
extern "C" void kernel_launch(void* const* d_in, const int* in_sizes, int n_in,
                              void* d_out, int out_size) {
    const float* x  = (const float*)d_in[0];
    const int*   ei = (const int*)d_in[1];
    const float* W1 = (const float*)d_in[2];
    const float* b1 = (const float*)d_in[3];
    const float* W2 = (const float*)d_in[4];
    const float* b2 = (const float*)d_in[5];
    float* out = (float*)d_out;

    const int T = 256;
    int nb_nodes = (N_NODES + T - 1) / T;
    int nb_edges2 = (N_EDGES / 2 + T - 1) / T;

    // Side stream + events for overlapping CSR build with GEMM1.
    cudaStream_t s2;
    cudaEvent_t ev_deg, ev_csr;
    cudaStreamCreateWithFlags(&s2, cudaStreamNonBlocking);
    cudaEventCreateWithFlags(&ev_deg, cudaEventDisableTiming);
    cudaEventCreateWithFlags(&ev_csr, cudaEventDisableTiming);

    // main stream: degree + dinv
    init_deg_kernel<<<nb_nodes, T>>>();
    count_deg_kernel<<<nb_edges2, T>>>(ei);
    dinv_kernel<<<nb_nodes, T>>>();
    cudaEventRecord(ev_deg, 0);

    // side stream: scan + CSR build (depends only on g_deg)
    cudaStreamWaitEvent(s2, ev_deg, 0);
    scan_partial_kernel<<<SCAN_NB, SCAN_T, 0, s2>>>();
    scan_blocksums_kernel<<<1, 1024, 0, s2>>>();
    scan_scatter_kernel<<<SCAN_NB, SCAN_T, 0, s2>>>();
    build_csr_kernel<<<nb_edges2, T, 0, s2>>>(ei);
    cudaEventRecord(ev_csr, s2);

    // main stream: GEMM1 in parallel with CSR build (needs only dinv)
    {
        dim3 grid((N_NODES + 127) / 128, HID / 128);
        gemm_f16_kernel<0><<<grid, 256>>>(x, W1, N_NODES, IN_CH, HID);
    }

    // join: SpMM1 needs CSR + hp1h
    cudaStreamWaitEvent(0, ev_csr, 0);
    {
        int blocks = (N_NODES * 32 + T - 1) / T;
        spmm_kernel<4, true, 0><<<blocks, T>>>(b1, nullptr);
    }
    {
        dim3 grid((N_NODES + 127) / 128, OUTC / 128);
        gemm_f16_kernel<1><<<grid, 256>>>(nullptr, W2, N_NODES, HID, OUTC);
    }
    {
        int blocks = (N_NODES * 32 + T - 1) / T;
        spmm_kernel<2, false, 1><<<blocks, T>>>(b2, out);
    }
}